// round 5
// baseline (speedup 1.0000x reference)
#include <cuda_runtime.h>

// Fully fused UpFIRDn2d, reordered: Vup -> (Hup + leaky + Hdn fused in regs) -> Vdn.
// Polyphase up taps (12-tap f, pl=5 correlation):
//   y[2m]   = sum e[k]*x[m-3+k] (k=0..6), e = {f0, f1+f2, f3+f4, f5+f6, f7+f8, f9+f10, f11}
//   y[2m+1] = sum o[k]*x[m-2+k] (k=0..5), o = {f0+f1, f2+f3, f4+f5, f6+f7, f8+f9, f10+f11}
// Upsampled coords valid only on [0,256) per axis; outside -> zero (dn-conv pad).
//
// SMEM (floats):
//   region A [0,2664):    s_x (46 x p45, rows 43-45 pad) S0/S1; t2 (74 x p36) S2/S3
//   region B [2664,6512): t1v (74 x p52) S1/S2
// Total 6512 floats = 26.0 KB.

#define NTHR 256
#define PX 45
#define PT 52
#define P2 36
#define RB_OFF 2664
#define SM_TOTAL (2664 + 74 * PT)   // 6512 floats

__global__ __launch_bounds__(NTHR, 4)
void upfirdn2d_fused_kernel(const float* __restrict__ x,
                            const float* __restrict__ bias,
                            const float* __restrict__ fup,
                            const float* __restrict__ fdn,
                            float* __restrict__ out)
{
    __shared__ float smem[SM_TOTAL];
    float* s_x  = smem;              // pitch 45 (S0-S1)
    float* s_t2 = smem;              // pitch 36 (S2-S3), aliases s_x
    float* s_t1 = smem + RB_OFF;     // pitch 52 (S1-S2)

    const int tid = threadIdx.x;
    const int bc  = blockIdx.y;
    const int Y0  = (blockIdx.x >> 2) * 32;
    const int X0  = (blockIdx.x & 3)  * 32;

    // polyphase up taps + dn taps
    float e[7], o[6], dn[12];
    {
        float up[12];
        #pragma unroll
        for (int k = 0; k < 12; k++) up[k] = fup[k];
        e[0] = up[0]; e[6] = up[11];
        #pragma unroll
        for (int j = 1; j < 6; j++) e[j] = up[2*j - 1] + up[2*j];
        #pragma unroll
        for (int j = 0; j < 6; j++) o[j] = up[2*j] + up[2*j + 1];
        #pragma unroll
        for (int k = 0; k < 12; k++) dn[k] = fdn[k];
    }
    const float bv = bias[bc & 63];
    const float* xin = x + (size_t)bc * (130 * 130);

    // ---- S0: input tile + halo (43 x 44), bias, zero pad ----
    {
        const int lane = tid & 31, w = tid >> 5;
        #pragma unroll
        for (int rr = 0; rr < 6; rr++) {
            int r = w + 8 * rr;
            if (r < 43) {
                int gy = Y0 - 5 + r;
                bool rowok = (unsigned)gy < 128u;
                const float* src = xin + (gy + 1) * 130 + (X0 - 5);
                float* dst = s_x + r * PX;
                #pragma unroll
                for (int ci = 0; ci < 2; ci++) {
                    int cc = lane + 32 * ci;
                    if (cc < 44) {
                        int gx = X0 - 6 + cc;
                        float v = 0.0f;
                        if (rowok && (unsigned)gx < 128u) v = src[cc] + bv;
                        dst[cc] = v;
                    }
                }
            }
        }
    }
    __syncthreads();

    // ---- S1: vertical polyphase up -> t1v[74][44] (pitch 52) ----
    // unit (g, col): row-pairs i = 4g..4g+3 (i<37); window x rows 4g..4g+9 (cols scalar).
    #pragma unroll
    for (int it = 0; it < 2; it++) {
        int u = tid + 256 * it;
        if (u < 10 * 44) {
            int g   = u / 44;
            int col = u - g * 44;
            const float* base = s_x + (4 * g) * PX + col;
            float w0 = base[0],      w1 = base[PX],     w2 = base[2*PX],
                  w3 = base[3*PX],   w4 = base[4*PX],   w5 = base[5*PX],
                  w6 = base[6*PX],   w7 = base[7*PX],   w8 = base[8*PX],
                  w9 = base[9*PX];
            float W[10] = {w0,w1,w2,w3,w4,w5,w6,w7,w8,w9};
            float* dst = s_t1 + (8 * g) * PT + col;
            #pragma unroll
            for (int p = 0; p < 4; p++) {
                int i = 4 * g + p;
                if (i < 37) {
                    int gr = 2 * Y0 - 5 + 2 * i;
                    float vo = 0.f, ve = 0.f;
                    if ((unsigned)gr < 256u)
                        vo = o[0]*W[p] + o[1]*W[p+1] + o[2]*W[p+2]
                           + o[3]*W[p+3] + o[4]*W[p+4] + o[5]*W[p+5];
                    if ((unsigned)(gr + 1) < 256u)
                        ve = e[0]*W[p] + e[1]*W[p+1] + e[2]*W[p+2] + e[3]*W[p+3]
                           + e[4]*W[p+4] + e[5]*W[p+5] + e[6]*W[p+6];
                    dst[(2 * p)     * PT] = vo;
                    dst[(2 * p + 1) * PT] = ve;
                }
            }
        }
    }
    __syncthreads();

    // ---- S2: fused Hup + leaky*gain + Hdn (stride-2) -> t2[74][32] ----
    // unit (t, row), row fast across lanes (pitch 52 tiles banks for LDS.128):
    // loads t1v[row][4t .. 4t+15], computes u[c] c=0..17 on the fly, accumulates
    // 4 outputs X = 4t..4t+3:  acc[q] += dn[c-2q]*u[c] for c in [2q, 2q+11].
    #pragma unroll
    for (int it = 0; it < 3; it++) {
        int u = tid + 256 * it;
        if (u < 8 * 74) {
            int t   = u / 74;
            int row = u - t * 74;
            const float4* b4 = reinterpret_cast<const float4*>(s_t1 + row * PT + 4 * t);
            float4 a0 = b4[0], a1 = b4[1], a2 = b4[2], a3 = b4[3];
            float xw[16] = {a0.x,a0.y,a0.z,a0.w, a1.x,a1.y,a1.z,a1.w,
                            a2.x,a2.y,a2.z,a2.w, a3.x,a3.y,a3.z,a3.w};
            const int gcb = 2 * X0 - 5 + 8 * t;
            float acc0 = 0.f, acc1 = 0.f, acc2 = 0.f, acc3 = 0.f;
            #pragma unroll
            for (int c = 0; c < 18; c++) {
                const int h = c >> 1;
                float v;
                if (c & 1) {   // gc even -> even phase, e taps (7-wide)
                    v = e[0]*xw[1+h] + e[1]*xw[2+h] + e[2]*xw[3+h] + e[3]*xw[4+h]
                      + e[4]*xw[5+h] + e[5]*xw[6+h] + e[6]*xw[7+h];
                } else {       // gc odd -> odd phase, o taps (6-wide)
                    v = o[0]*xw[1+h] + o[1]*xw[2+h] + o[2]*xw[3+h]
                      + o[3]*xw[4+h] + o[4]*xw[5+h] + o[5]*xw[6+h];
                }
                int gc = gcb + c;
                v = ((unsigned)gc < 256u) ? v : 0.f;
                const float G = 1.41421356237309515f;
                float uu = (v >= 0.f) ? v * G : v * (0.2f * G);
                if (c <= 11)           acc0 += dn[c]     * uu;
                if (c >= 2 && c <= 13) acc1 += dn[c - 2] * uu;
                if (c >= 4 && c <= 15) acc2 += dn[c - 4] * uu;
                if (c >= 6)            acc3 += dn[c - 6] * uu;
            }
            *reinterpret_cast<float4*>(s_t2 + row * P2 + 4 * t) =
                make_float4(acc0, acc1, acc2, acc3);
        }
    }
    __syncthreads();

    // ---- S3: vertical dn-conv, stride-2 -> out; 4 rows x 1 col per thread ----
    {
        int Xl = tid & 31;
        int g  = tid >> 5;                 // 0..7 -> out rows 4g..4g+3
        const float* col = s_t2 + (8 * g) * P2 + Xl;
        float R[18];
        #pragma unroll
        for (int k = 0; k < 18; k++) R[k] = col[k * P2];
        float* op = out + ((size_t)bc * 128 + (Y0 + 4 * g)) * 128 + X0 + Xl;
        #pragma unroll
        for (int q = 0; q < 4; q++) {
            float v = 0.f;
            #pragma unroll
            for (int k = 0; k < 12; k++) v += dn[k] * R[2*q + k];
            op[q * 128] = v;
        }
    }
}

extern "C" void kernel_launch(void* const* d_in, const int* in_sizes, int n_in,
                              void* d_out, int out_size)
{
    const float* x    = (const float*)d_in[0];   // (8,64,130,130) fp32
    const float* bias = (const float*)d_in[1];   // (64,) fp32
    const float* fup  = (const float*)d_in[2];   // (12,) fp32
    const float* fdn  = (const float*)d_in[3];   // (12,) fp32
    float* out = (float*)d_out;                  // (8,64,128,128) fp32

    dim3 grid(16, 512);
    upfirdn2d_fused_kernel<<<grid, NTHR>>>(x, bias, fup, fdn, out);
}

// round 6
// speedup vs baseline: 1.2405x; 1.2405x over previous
#include <cuda_runtime.h>

// Fully fused UpFIRDn2d (crop -> bias -> up2 -> sep FIR12 -> leaky*sqrt2 -> sep FIR12 -> dn2)
// Polyphase up taps (pl=5 correlation):
//   y[2m]   = sum e[k]*x[m-3+k] (k=0..6), e = {f0, f1+f2, f3+f4, f5+f6, f7+f8, f9+f10, f11}
//   y[2m+1] = sum o[k]*x[m-2+k] (k=0..5), o = {f0+f1, f2+f3, f4+f5, f6+f7, f8+f9, f10+f11}
// Upsampled coords valid only on [0,256) per axis; outside -> 0 (dn-conv pad).
//
// SMEM regions (floats), aliased by lifetime:
//   A [0,5624):     s_x (43 x p46) S0/S1;  a (74 x p76) S2/S3
//   B [5624,9120):  t1 (46 x p76, rows 43-45 pad/garbage but guarded) S1/S2;
//                   t2 (74 x p36) S3/S4
// Total 9120 floats = 36.5 KB -> 5 CTAs/SM.

#define NTHR 256
#define PX 46
#define PT 76
#define P2 36
#define RB_OFF 5624
#define SM_TOTAL (5624 + 46 * PT)   // 9120 floats

__global__ __launch_bounds__(NTHR, 5)
void upfirdn2d_fused_kernel(const float* __restrict__ x,
                            const float* __restrict__ bias,
                            const float* __restrict__ fup,
                            const float* __restrict__ fdn,
                            float* __restrict__ out)
{
    __shared__ float smem[SM_TOTAL];
    float* s_x  = smem;              // pitch 46 (S0-S1)
    float* s_a  = smem;              // pitch 76 (S2-S3), aliases s_x
    float* s_t1 = smem + RB_OFF;     // pitch 76 (S1-S2)
    float* s_t2 = smem + RB_OFF;     // pitch 36 (S3-S4), aliases t1

    const int tid = threadIdx.x;
    const int bc  = blockIdx.y;
    const int Y0  = (blockIdx.x >> 2) * 32;
    const int X0  = (blockIdx.x & 3)  * 32;

    // polyphase up taps
    float e[7], o[6];
    {
        float up[12];
        #pragma unroll
        for (int k = 0; k < 12; k++) up[k] = fup[k];
        e[0] = up[0]; e[6] = up[11];
        #pragma unroll
        for (int j = 1; j < 6; j++) e[j] = up[2*j - 1] + up[2*j];
        #pragma unroll
        for (int j = 0; j < 6; j++) o[j] = up[2*j] + up[2*j + 1];
    }
    const float bv = bias[bc & 63];
    const float* xin = x + (size_t)bc * (130 * 130);

    // ---- S0: input tile + halo (43 x 44), bias, zero pad ----
    {
        const int lane = tid & 31, w = tid >> 5;
        #pragma unroll
        for (int rr = 0; rr < 6; rr++) {
            int r = w + 8 * rr;
            if (r < 43) {
                int gy = Y0 - 5 + r;
                bool rowok = (unsigned)gy < 128u;
                const float* src = xin + (gy + 1) * 130 + (X0 - 5);
                float* dst = s_x + r * PX;
                #pragma unroll
                for (int ci = 0; ci < 2; ci++) {
                    int cc = lane + 32 * ci;
                    if (cc < 44) {
                        int gx = X0 - 6 + cc;
                        float v = 0.0f;
                        if (rowok && (unsigned)gx < 128u) v = src[cc] + bv;
                        dst[cc] = v;
                    }
                }
            }
        }
    }
    __syncthreads();

    // ---- S1: horizontal polyphase up -> t1[43][74], 4 pairs (8 outputs)/unit ----
    // unit (r, tp): pairs j = 4tp..4tp+3; window x cols 4tp..4tp+11 (6 float2).
    // pair j: vo/ve from xw[p+1 .. p+7] (p = j-4tp); t1 cols 2j, 2j+1.
    #pragma unroll
    for (int it = 0; it < 2; it++) {
        int u = tid + 256 * it;
        if (u < 43 * 10) {
            int r  = u / 10;
            int tp = u - r * 10;
            const float2* row2 = reinterpret_cast<const float2*>(s_x + r * PX + 4 * tp);
            float2 q0 = row2[0], q1 = row2[1], q2 = row2[2],
                   q3 = row2[3], q4 = row2[4], q5 = row2[5];
            float xw[12] = {q0.x,q0.y,q1.x,q1.y,q2.x,q2.y,
                            q3.x,q3.y,q4.x,q4.y,q5.x,q5.y};
            const int gcb = 2 * X0 - 5 + 8 * tp;
            float res[8];
            #pragma unroll
            for (int p = 0; p < 4; p++) {
                float vo = o[0]*xw[p+1] + o[1]*xw[p+2] + o[2]*xw[p+3]
                         + o[3]*xw[p+4] + o[4]*xw[p+5] + o[5]*xw[p+6];
                float ve = e[0]*xw[p+1] + e[1]*xw[p+2] + e[2]*xw[p+3] + e[3]*xw[p+4]
                         + e[4]*xw[p+5] + e[5]*xw[p+6] + e[6]*xw[p+7];
                int gc = gcb + 2 * p;
                res[2*p]     = ((unsigned)gc       < 256u) ? vo : 0.f;
                res[2*p + 1] = ((unsigned)(gc + 1) < 256u) ? ve : 0.f;
            }
            float* dst = s_t1 + r * PT + 8 * tp;
            if (tp < 9) {
                *reinterpret_cast<float4*>(dst)     = make_float4(res[0],res[1],res[2],res[3]);
                *reinterpret_cast<float4*>(dst + 4) = make_float4(res[4],res[5],res[6],res[7]);
            } else {  // only pair 36 exists in this group
                *reinterpret_cast<float2*>(dst) = make_float2(res[0], res[1]);
            }
        }
    }

    // fold leaky gain sqrt(2) into up taps (sign test invariant under positive scale)
    {
        const float G = 1.41421356237309515f;
        #pragma unroll
        for (int k = 0; k < 7; k++) e[k] *= G;
        #pragma unroll
        for (int k = 0; k < 6; k++) o[k] *= G;
    }
    __syncthreads();

    // ---- S2: vertical polyphase up + leaky -> a[74][74] ----
    // unit (g, ac2): col-pair (2ac2, 2ac2+1), row-pairs i = 4g..4g+3 (i<37).
    // Window: t1 rows 4g..4g+9 (10 float2 loads); t1 rows 43-45 garbage but guarded.
    #pragma unroll
    for (int it = 0; it < 2; it++) {
        int u = tid + 256 * it;
        if (u < 10 * 37) {
            int g   = u / 37;
            int ac2 = u - g * 37;
            const float* base = s_t1 + (4 * g) * PT + 2 * ac2;
            float2 W[10];
            #pragma unroll
            for (int k = 0; k < 10; k++)
                W[k] = *reinterpret_cast<const float2*>(base + k * PT);
            float* adst = s_a + (8 * g) * PT + 2 * ac2;
            #pragma unroll
            for (int p = 0; p < 4; p++) {
                int i = 4 * g + p;
                if (i < 37) {
                    int gr = 2 * Y0 - 5 + 2 * i;
                    float vox = 0.f, voy = 0.f, vex = 0.f, vey = 0.f;
                    if ((unsigned)gr < 256u) {
                        vox = o[0]*W[p].x + o[1]*W[p+1].x + o[2]*W[p+2].x
                            + o[3]*W[p+3].x + o[4]*W[p+4].x + o[5]*W[p+5].x;
                        voy = o[0]*W[p].y + o[1]*W[p+1].y + o[2]*W[p+2].y
                            + o[3]*W[p+3].y + o[4]*W[p+4].y + o[5]*W[p+5].y;
                    }
                    if ((unsigned)(gr + 1) < 256u) {
                        vex = e[0]*W[p].x + e[1]*W[p+1].x + e[2]*W[p+2].x + e[3]*W[p+3].x
                            + e[4]*W[p+4].x + e[5]*W[p+5].x + e[6]*W[p+6].x;
                        vey = e[0]*W[p].y + e[1]*W[p+1].y + e[2]*W[p+2].y + e[3]*W[p+3].y
                            + e[4]*W[p+4].y + e[5]*W[p+5].y + e[6]*W[p+6].y;
                    }
                    float2 ro, re;
                    ro.x = (vox >= 0.f) ? vox : 0.2f * vox;
                    ro.y = (voy >= 0.f) ? voy : 0.2f * voy;
                    re.x = (vex >= 0.f) ? vex : 0.2f * vex;
                    re.y = (vey >= 0.f) ? vey : 0.2f * vey;
                    *reinterpret_cast<float2*>(adst + (2 * p)     * PT) = ro;
                    *reinterpret_cast<float2*>(adst + (2 * p + 1) * PT) = re;
                }
            }
        }
    }
    __syncthreads();

    // dn filter loaded here so its registers don't extend e/o liveness
    float dn[12];
    #pragma unroll
    for (int k = 0; k < 12; k++) dn[k] = fdn[k];

    // ---- S3: horizontal dn-conv, stride-2 -> t2[74][32], 8 outputs/unit, streamed ----
    // unit (t, ar): outputs X = 8t..8t+7; reads a[ar][16t .. 16t+27] as 7 float4.
    // (elements c=26,27 feed no accumulator; a cols 74,75 are never accumulated.)
    // ar fast across lanes (stride 304B = conflict-free for LDS.128).
    #pragma unroll
    for (int it = 0; it < 2; it++) {
        int u = tid + 256 * it;
        if (u < 4 * 74) {
            int t  = u / 74;
            int ar = u - t * 74;
            const float4* row = reinterpret_cast<const float4*>(s_a + ar * PT + 16 * t);
            float acc[8] = {0.f,0.f,0.f,0.f,0.f,0.f,0.f,0.f};
            #pragma unroll
            for (int j = 0; j < 7; j++) {
                float4 qv = row[j];
                float el[4] = {qv.x, qv.y, qv.z, qv.w};
                #pragma unroll
                for (int m = 0; m < 4; m++) {
                    const int c = 4 * j + m;
                    #pragma unroll
                    for (int q = 0; q < 8; q++) {
                        const int k = c - 2 * q;
                        if (k >= 0 && k < 12) acc[q] += dn[k] * el[m];
                    }
                }
            }
            float* dst = s_t2 + ar * P2 + 8 * t;
            *reinterpret_cast<float4*>(dst)     = make_float4(acc[0],acc[1],acc[2],acc[3]);
            *reinterpret_cast<float4*>(dst + 4) = make_float4(acc[4],acc[5],acc[6],acc[7]);
        }
    }
    __syncthreads();

    // ---- S4: vertical dn-conv, stride-2 -> out; 4 rows x 2 cols per thread ----
    if (tid < 128) {
        int cp = tid & 15;          // col-pair: Xl = 2*cp
        int yg = tid >> 4;          // y0 = 4*yg
        const float* base = s_t2 + (8 * yg) * P2 + 2 * cp;
        float2 R[18];
        #pragma unroll
        for (int k = 0; k < 18; k++)
            R[k] = *reinterpret_cast<const float2*>(base + k * P2);
        float* op = out + ((size_t)bc * 128 + (Y0 + 4 * yg)) * 128 + X0 + 2 * cp;
        #pragma unroll
        for (int q = 0; q < 4; q++) {
            float sx = 0.f, sy = 0.f;
            #pragma unroll
            for (int k = 0; k < 12; k++) {
                sx += dn[k] * R[2*q + k].x;
                sy += dn[k] * R[2*q + k].y;
            }
            *reinterpret_cast<float2*>(op + q * 128) = make_float2(sx, sy);
        }
    }
}

extern "C" void kernel_launch(void* const* d_in, const int* in_sizes, int n_in,
                              void* d_out, int out_size)
{
    const float* x    = (const float*)d_in[0];   // (8,64,130,130) fp32
    const float* bias = (const float*)d_in[1];   // (64,) fp32
    const float* fup  = (const float*)d_in[2];   // (12,) fp32
    const float* fdn  = (const float*)d_in[3];   // (12,) fp32
    float* out = (float*)d_out;                  // (8,64,128,128) fp32

    dim3 grid(16, 512);
    upfirdn2d_fused_kernel<<<grid, NTHR>>>(x, bias, fup, fdn, out);
}

// round 7
// speedup vs baseline: 1.2411x; 1.0004x over previous
#include <cuda_runtime.h>

// Fully fused UpFIRDn2d (crop -> bias -> up2 -> sep FIR12 -> leaky*sqrt2 -> sep FIR12 -> dn2)
// Polyphase up taps (pl=5 correlation):
//   y[2m]   = sum e[k]*x[m-3+k] (k=0..6), e = {f0, f1+f2, f3+f4, f5+f6, f7+f8, f9+f10, f11}
//   y[2m+1] = sum o[k]*x[m-2+k] (k=0..5), o = {f0+f1, f2+f3, f4+f5, f6+f7, f8+f9, f10+f11}
// Upsampled coords valid only on [0,256) per axis; outside -> 0 (dn-conv pad).
// Edge clamps only matter for X0 in {0,96} / Y0 in {0,96}: interior tiles take
// a clamp-free fast path (block-uniform branch).
//
// SMEM regions (floats), aliased by lifetime:
//   A [0,5624):     s_x (43 x p46) S0/S1;  a (74 x p76) S2/S3
//   B [5624,9120):  t1 (46 x p76, rows 43-45 garbage but guarded) S1/S2;
//                   t2 (74 x p36) S3/S4
// Total 9120 floats = 36.5 KB -> 5 CTAs/SM (reg-capped at 5: 47 regs).

#define NTHR 256
#define PX 46
#define PT 76
#define P2 36
#define RB_OFF 5624
#define SM_TOTAL (5624 + 46 * PT)   // 9120 floats

__global__ __launch_bounds__(NTHR, 5)
void upfirdn2d_fused_kernel(const float* __restrict__ x,
                            const float* __restrict__ bias,
                            const float* __restrict__ fup,
                            const float* __restrict__ fdn,
                            float* __restrict__ out)
{
    __shared__ float smem[SM_TOTAL];
    float* s_x  = smem;              // pitch 46 (S0-S1)
    float* s_a  = smem;              // pitch 76 (S2-S3), aliases s_x
    float* s_t1 = smem + RB_OFF;     // pitch 76 (S1-S2)
    float* s_t2 = smem + RB_OFF;     // pitch 36 (S3-S4), aliases t1

    const int tid = threadIdx.x;
    const int bc  = blockIdx.y;
    const int Y0  = (blockIdx.x >> 2) * 32;
    const int X0  = (blockIdx.x & 3)  * 32;
    const bool x_int = (X0 != 0) && (X0 != 96);   // all gc in [0,256)
    const bool y_int = (Y0 != 0) && (Y0 != 96);   // all gr in [0,256)

    // polyphase up taps
    float e[7], o[6];
    {
        float up[12];
        #pragma unroll
        for (int k = 0; k < 12; k++) up[k] = fup[k];
        e[0] = up[0]; e[6] = up[11];
        #pragma unroll
        for (int j = 1; j < 6; j++) e[j] = up[2*j - 1] + up[2*j];
        #pragma unroll
        for (int j = 0; j < 6; j++) o[j] = up[2*j] + up[2*j + 1];
    }
    const float bv = bias[bc & 63];
    const float* xin = x + (size_t)bc * (130 * 130);

    // ---- S0: input tile + halo (43 x 44), bias, zero pad ----
    {
        const int lane = tid & 31, w = tid >> 5;
        if (x_int && y_int) {
            #pragma unroll
            for (int rr = 0; rr < 6; rr++) {
                int r = w + 8 * rr;
                if (r < 43) {
                    const float* src = xin + (Y0 - 4 + r) * 130 + (X0 - 5);
                    float* dst = s_x + r * PX;
                    #pragma unroll
                    for (int ci = 0; ci < 2; ci++) {
                        int cc = lane + 32 * ci;
                        if (cc < 44) dst[cc] = src[cc] + bv;
                    }
                }
            }
        } else {
            #pragma unroll
            for (int rr = 0; rr < 6; rr++) {
                int r = w + 8 * rr;
                if (r < 43) {
                    int gy = Y0 - 5 + r;
                    bool rowok = (unsigned)gy < 128u;
                    const float* src = xin + (gy + 1) * 130 + (X0 - 5);
                    float* dst = s_x + r * PX;
                    #pragma unroll
                    for (int ci = 0; ci < 2; ci++) {
                        int cc = lane + 32 * ci;
                        if (cc < 44) {
                            int gx = X0 - 6 + cc;
                            float v = 0.0f;
                            if (rowok && (unsigned)gx < 128u) v = src[cc] + bv;
                            dst[cc] = v;
                        }
                    }
                }
            }
        }
    }
    __syncthreads();

    // ---- S1: horizontal polyphase up -> t1[43][74] ----
    // unit (r, tp in 0..8): pairs j = 4tp..4tp+3, plus pair 36 when tp==8.
    // Window x cols 4tp..4tp+11 (6 float2); pair 36's window (cols 37..43) fits.
    #pragma unroll
    for (int it = 0; it < 2; it++) {
        int u = tid + 256 * it;
        if (u < 43 * 9) {
            int r  = u / 9;
            int tp = u - r * 9;
            const float2* row2 = reinterpret_cast<const float2*>(s_x + r * PX + 4 * tp);
            float2 q0 = row2[0], q1 = row2[1], q2 = row2[2],
                   q3 = row2[3], q4 = row2[4], q5 = row2[5];
            float xw[12] = {q0.x,q0.y,q1.x,q1.y,q2.x,q2.y,
                            q3.x,q3.y,q4.x,q4.y,q5.x,q5.y};
            float res[8];
            #pragma unroll
            for (int p = 0; p < 4; p++) {
                float vo = o[0]*xw[p+1] + o[1]*xw[p+2] + o[2]*xw[p+3]
                         + o[3]*xw[p+4] + o[4]*xw[p+5] + o[5]*xw[p+6];
                float ve = e[0]*xw[p+1] + e[1]*xw[p+2] + e[2]*xw[p+3] + e[3]*xw[p+4]
                         + e[4]*xw[p+5] + e[5]*xw[p+6] + e[6]*xw[p+7];
                if (!x_int) {
                    int gc = 2 * X0 - 5 + 8 * tp + 2 * p;
                    vo = ((unsigned)gc       < 256u) ? vo : 0.f;
                    ve = ((unsigned)(gc + 1) < 256u) ? ve : 0.f;
                }
                res[2*p] = vo; res[2*p + 1] = ve;
            }
            float* dst = s_t1 + r * PT + 8 * tp;
            *reinterpret_cast<float4*>(dst)     = make_float4(res[0],res[1],res[2],res[3]);
            *reinterpret_cast<float4*>(dst + 4) = make_float4(res[4],res[5],res[6],res[7]);
            if (tp == 8) {   // pair 36 -> t1 cols 72,73; window xw[5..11]
                float vo = o[0]*xw[5] + o[1]*xw[6] + o[2]*xw[7]
                         + o[3]*xw[8] + o[4]*xw[9] + o[5]*xw[10];
                float ve = e[0]*xw[5] + e[1]*xw[6] + e[2]*xw[7] + e[3]*xw[8]
                         + e[4]*xw[9] + e[5]*xw[10] + e[6]*xw[11];
                if (!x_int) {
                    int gc = 2 * X0 - 5 + 72;
                    vo = ((unsigned)gc       < 256u) ? vo : 0.f;
                    ve = ((unsigned)(gc + 1) < 256u) ? ve : 0.f;
                }
                *reinterpret_cast<float2*>(dst + 8) = make_float2(vo, ve);
            }
        }
    }

    // fold leaky gain sqrt(2) into up taps (sign test invariant under positive scale)
    {
        const float G = 1.41421356237309515f;
        #pragma unroll
        for (int k = 0; k < 7; k++) e[k] *= G;
        #pragma unroll
        for (int k = 0; k < 6; k++) o[k] *= G;
    }
    __syncthreads();

    // ---- S2: vertical polyphase up + leaky -> a[74][74] ----
    // unit (g, ac2): col-pair (2ac2, 2ac2+1), row-pairs i = 4g..4g+3 (i<37 guards
    // the garbage t1 rows 43-45). Compute always; clamp only on y-edge tiles.
    #pragma unroll
    for (int it = 0; it < 2; it++) {
        int u = tid + 256 * it;
        if (u < 10 * 37) {
            int g   = u / 37;
            int ac2 = u - g * 37;
            const float* base = s_t1 + (4 * g) * PT + 2 * ac2;
            float2 W[10];
            #pragma unroll
            for (int k = 0; k < 10; k++)
                W[k] = *reinterpret_cast<const float2*>(base + k * PT);
            float* adst = s_a + (8 * g) * PT + 2 * ac2;
            #pragma unroll
            for (int p = 0; p < 4; p++) {
                int i = 4 * g + p;
                if (i < 37) {
                    float vox = o[0]*W[p].x + o[1]*W[p+1].x + o[2]*W[p+2].x
                              + o[3]*W[p+3].x + o[4]*W[p+4].x + o[5]*W[p+5].x;
                    float voy = o[0]*W[p].y + o[1]*W[p+1].y + o[2]*W[p+2].y
                              + o[3]*W[p+3].y + o[4]*W[p+4].y + o[5]*W[p+5].y;
                    float vex = e[0]*W[p].x + e[1]*W[p+1].x + e[2]*W[p+2].x + e[3]*W[p+3].x
                              + e[4]*W[p+4].x + e[5]*W[p+5].x + e[6]*W[p+6].x;
                    float vey = e[0]*W[p].y + e[1]*W[p+1].y + e[2]*W[p+2].y + e[3]*W[p+3].y
                              + e[4]*W[p+4].y + e[5]*W[p+5].y + e[6]*W[p+6].y;
                    if (!y_int) {
                        int gr = 2 * Y0 - 5 + 2 * i;
                        bool ok0 = (unsigned)gr       < 256u;
                        bool ok1 = (unsigned)(gr + 1) < 256u;
                        vox = ok0 ? vox : 0.f;  voy = ok0 ? voy : 0.f;
                        vex = ok1 ? vex : 0.f;  vey = ok1 ? vey : 0.f;
                    }
                    float2 ro, re;
                    ro.x = (vox >= 0.f) ? vox : 0.2f * vox;
                    ro.y = (voy >= 0.f) ? voy : 0.2f * voy;
                    re.x = (vex >= 0.f) ? vex : 0.2f * vex;
                    re.y = (vey >= 0.f) ? vey : 0.2f * vey;
                    *reinterpret_cast<float2*>(adst + (2 * p)     * PT) = ro;
                    *reinterpret_cast<float2*>(adst + (2 * p + 1) * PT) = re;
                }
            }
        }
    }
    __syncthreads();

    // dn filter loaded here so its registers don't extend e/o liveness
    float dn[12];
    #pragma unroll
    for (int k = 0; k < 12; k++) dn[k] = fdn[k];

    // ---- S3: horizontal dn-conv, stride-2 -> t2[74][32], 8 outputs/unit, streamed ----
    // unit (t, ar): outputs X = 8t..8t+7; reads a[ar][16t .. 16t+27] as 7 float4.
    // ar fast across lanes (stride 304B = conflict-free for LDS.128).
    #pragma unroll
    for (int it = 0; it < 2; it++) {
        int u = tid + 256 * it;
        if (u < 4 * 74) {
            int t  = u / 74;
            int ar = u - t * 74;
            const float4* row = reinterpret_cast<const float4*>(s_a + ar * PT + 16 * t);
            float acc[8] = {0.f,0.f,0.f,0.f,0.f,0.f,0.f,0.f};
            #pragma unroll
            for (int j = 0; j < 7; j++) {
                float4 qv = row[j];
                float el[4] = {qv.x, qv.y, qv.z, qv.w};
                #pragma unroll
                for (int m = 0; m < 4; m++) {
                    const int c = 4 * j + m;
                    #pragma unroll
                    for (int q = 0; q < 8; q++) {
                        const int k = c - 2 * q;
                        if (k >= 0 && k < 12) acc[q] += dn[k] * el[m];
                    }
                }
            }
            float* dst = s_t2 + ar * P2 + 8 * t;
            *reinterpret_cast<float4*>(dst)     = make_float4(acc[0],acc[1],acc[2],acc[3]);
            *reinterpret_cast<float4*>(dst + 4) = make_float4(acc[4],acc[5],acc[6],acc[7]);
        }
    }
    __syncthreads();

    // ---- S4: vertical dn-conv, stride-2 -> out; 4 rows x 2 cols per thread ----
    if (tid < 128) {
        int cp = tid & 15;          // col-pair: Xl = 2*cp
        int yg = tid >> 4;          // y0 = 4*yg
        const float* base = s_t2 + (8 * yg) * P2 + 2 * cp;
        float2 R[18];
        #pragma unroll
        for (int k = 0; k < 18; k++)
            R[k] = *reinterpret_cast<const float2*>(base + k * P2);
        float* op = out + ((size_t)bc * 128 + (Y0 + 4 * yg)) * 128 + X0 + 2 * cp;
        #pragma unroll
        for (int q = 0; q < 4; q++) {
            float sx = 0.f, sy = 0.f;
            #pragma unroll
            for (int k = 0; k < 12; k++) {
                sx += dn[k] * R[2*q + k].x;
                sy += dn[k] * R[2*q + k].y;
            }
            *reinterpret_cast<float2*>(op + q * 128) = make_float2(sx, sy);
        }
    }
}

extern "C" void kernel_launch(void* const* d_in, const int* in_sizes, int n_in,
                              void* d_out, int out_size)
{
    const float* x    = (const float*)d_in[0];   // (8,64,130,130) fp32
    const float* bias = (const float*)d_in[1];   // (64,) fp32
    const float* fup  = (const float*)d_in[2];   // (12,) fp32
    const float* fdn  = (const float*)d_in[3];   // (12,) fp32
    float* out = (float*)d_out;                  // (8,64,128,128) fp32

    dim3 grid(16, 512);
    upfirdn2d_fused_kernel<<<grid, NTHR>>>(x, bias, fup, fdn, out);
}

// round 8
// speedup vs baseline: 1.2763x; 1.0284x over previous
#include <cuda_runtime.h>

// Fully fused UpFIRDn2d (crop -> bias -> up2 -> sep FIR12 -> leaky*sqrt2 -> sep FIR12 -> dn2)
// Polyphase up taps (pl=5 correlation):
//   y[2m]   = sum e[k]*x[m-3+k] (k=0..6), e = {f0, f1+f2, f3+f4, f5+f6, f7+f8, f9+f10, f11}
//   y[2m+1] = sum o[k]*x[m-2+k] (k=0..5), o = {f0+f1, f2+f3, f4+f5, f6+f7, f8+f9, f10+f11}
// Upsampled coords valid only on [0,256) per axis; outside -> 0 (dn-conv pad).
// S3/S4 use packed fp32x2 FMA (fma.rn.f32x2) — both operands naturally paired.
//
// SMEM regions (floats), aliased by lifetime:
//   A [0,5624):     s_x (43 x p46) S0/S1;  a (74 x p76) S2/S3
//   B [5624,9120):  t1 (46 x p76, rows 43-45 garbage but guarded) S1/S2;
//                   t2 (74 x p36) S3/S4
// Total 9120 floats = 36.5 KB -> 5 CTAs/SM.

#define NTHR 256
#define PX 46
#define PT 76
#define P2 36
#define RB_OFF 5624
#define SM_TOTAL (5624 + 46 * PT)   // 9120 floats

typedef unsigned long long u64;

__device__ __forceinline__ u64 pk2(float lo, float hi) {
    u64 r; asm("mov.b64 %0, {%1, %2};" : "=l"(r) : "f"(lo), "f"(hi)); return r;
}
__device__ __forceinline__ void upk2(u64 v, float& lo, float& hi) {
    asm("mov.b64 {%0, %1}, %2;" : "=f"(lo), "=f"(hi) : "l"(v));
}
__device__ __forceinline__ u64 ffma2(u64 a, u64 b, u64 c) {
    u64 d; asm("fma.rn.f32x2 %0, %1, %2, %3;" : "=l"(d) : "l"(a), "l"(b), "l"(c)); return d;
}

__global__ __launch_bounds__(NTHR, 5)
void upfirdn2d_fused_kernel(const float* __restrict__ x,
                            const float* __restrict__ bias,
                            const float* __restrict__ fup,
                            const float* __restrict__ fdn,
                            float* __restrict__ out)
{
    __shared__ float smem[SM_TOTAL];
    float* s_x  = smem;              // pitch 46 (S0-S1)
    float* s_a  = smem;              // pitch 76 (S2-S3), aliases s_x
    float* s_t1 = smem + RB_OFF;     // pitch 76 (S1-S2)
    float* s_t2 = smem + RB_OFF;     // pitch 36 (S3-S4), aliases t1

    const int tid = threadIdx.x;
    const int bc  = blockIdx.y;
    const int Y0  = (blockIdx.x >> 2) * 32;
    const int X0  = (blockIdx.x & 3)  * 32;
    const bool x_int = (X0 != 0) && (X0 != 96);
    const bool y_int = (Y0 != 0) && (Y0 != 96);

    // polyphase up taps
    float e[7], o[6];
    {
        float up[12];
        #pragma unroll
        for (int k = 0; k < 12; k++) up[k] = fup[k];
        e[0] = up[0]; e[6] = up[11];
        #pragma unroll
        for (int j = 1; j < 6; j++) e[j] = up[2*j - 1] + up[2*j];
        #pragma unroll
        for (int j = 0; j < 6; j++) o[j] = up[2*j] + up[2*j + 1];
    }
    const float bv = bias[bc & 63];
    const float* xin = x + (size_t)bc * (130 * 130);

    // ---- S0: input tile + halo (43 x 44), bias, zero pad ----
    {
        const int lane = tid & 31, w = tid >> 5;
        if (x_int && y_int) {
            #pragma unroll
            for (int rr = 0; rr < 6; rr++) {
                int r = w + 8 * rr;
                if (r < 43) {
                    const float* src = xin + (Y0 - 4 + r) * 130 + (X0 - 5);
                    float* dst = s_x + r * PX;
                    #pragma unroll
                    for (int ci = 0; ci < 2; ci++) {
                        int cc = lane + 32 * ci;
                        if (cc < 44) dst[cc] = src[cc] + bv;
                    }
                }
            }
        } else {
            #pragma unroll
            for (int rr = 0; rr < 6; rr++) {
                int r = w + 8 * rr;
                if (r < 43) {
                    int gy = Y0 - 5 + r;
                    bool rowok = (unsigned)gy < 128u;
                    const float* src = xin + (gy + 1) * 130 + (X0 - 5);
                    float* dst = s_x + r * PX;
                    #pragma unroll
                    for (int ci = 0; ci < 2; ci++) {
                        int cc = lane + 32 * ci;
                        if (cc < 44) {
                            int gx = X0 - 6 + cc;
                            float v = 0.0f;
                            if (rowok && (unsigned)gx < 128u) v = src[cc] + bv;
                            dst[cc] = v;
                        }
                    }
                }
            }
        }
    }
    __syncthreads();

    // ---- S1: horizontal polyphase up -> t1[43][74] ----
    #pragma unroll
    for (int it = 0; it < 2; it++) {
        int u = tid + 256 * it;
        if (u < 43 * 9) {
            int r  = u / 9;
            int tp = u - r * 9;
            const float2* row2 = reinterpret_cast<const float2*>(s_x + r * PX + 4 * tp);
            float2 q0 = row2[0], q1 = row2[1], q2 = row2[2],
                   q3 = row2[3], q4 = row2[4], q5 = row2[5];
            float xw[12] = {q0.x,q0.y,q1.x,q1.y,q2.x,q2.y,
                            q3.x,q3.y,q4.x,q4.y,q5.x,q5.y};
            float res[8];
            #pragma unroll
            for (int p = 0; p < 4; p++) {
                float vo = o[0]*xw[p+1] + o[1]*xw[p+2] + o[2]*xw[p+3]
                         + o[3]*xw[p+4] + o[4]*xw[p+5] + o[5]*xw[p+6];
                float ve = e[0]*xw[p+1] + e[1]*xw[p+2] + e[2]*xw[p+3] + e[3]*xw[p+4]
                         + e[4]*xw[p+5] + e[5]*xw[p+6] + e[6]*xw[p+7];
                if (!x_int) {
                    int gc = 2 * X0 - 5 + 8 * tp + 2 * p;
                    vo = ((unsigned)gc       < 256u) ? vo : 0.f;
                    ve = ((unsigned)(gc + 1) < 256u) ? ve : 0.f;
                }
                res[2*p] = vo; res[2*p + 1] = ve;
            }
            float* dst = s_t1 + r * PT + 8 * tp;
            *reinterpret_cast<float4*>(dst)     = make_float4(res[0],res[1],res[2],res[3]);
            *reinterpret_cast<float4*>(dst + 4) = make_float4(res[4],res[5],res[6],res[7]);
            if (tp == 8) {   // pair 36 -> t1 cols 72,73; window xw[5..11]
                float vo = o[0]*xw[5] + o[1]*xw[6] + o[2]*xw[7]
                         + o[3]*xw[8] + o[4]*xw[9] + o[5]*xw[10];
                float ve = e[0]*xw[5] + e[1]*xw[6] + e[2]*xw[7] + e[3]*xw[8]
                         + e[4]*xw[9] + e[5]*xw[10] + e[6]*xw[11];
                if (!x_int) {
                    int gc = 2 * X0 - 5 + 72;
                    vo = ((unsigned)gc       < 256u) ? vo : 0.f;
                    ve = ((unsigned)(gc + 1) < 256u) ? ve : 0.f;
                }
                *reinterpret_cast<float2*>(dst + 8) = make_float2(vo, ve);
            }
        }
    }

    // fold leaky gain sqrt(2) into up taps
    {
        const float G = 1.41421356237309515f;
        #pragma unroll
        for (int k = 0; k < 7; k++) e[k] *= G;
        #pragma unroll
        for (int k = 0; k < 6; k++) o[k] *= G;
    }
    __syncthreads();

    // ---- S2: vertical polyphase up + leaky -> a[74][74] ----
    #pragma unroll
    for (int it = 0; it < 2; it++) {
        int u = tid + 256 * it;
        if (u < 10 * 37) {
            int g   = u / 37;
            int ac2 = u - g * 37;
            const float* base = s_t1 + (4 * g) * PT + 2 * ac2;
            float2 W[10];
            #pragma unroll
            for (int k = 0; k < 10; k++)
                W[k] = *reinterpret_cast<const float2*>(base + k * PT);
            float* adst = s_a + (8 * g) * PT + 2 * ac2;
            #pragma unroll
            for (int p = 0; p < 4; p++) {
                int i = 4 * g + p;
                if (i < 37) {
                    float vox = o[0]*W[p].x + o[1]*W[p+1].x + o[2]*W[p+2].x
                              + o[3]*W[p+3].x + o[4]*W[p+4].x + o[5]*W[p+5].x;
                    float voy = o[0]*W[p].y + o[1]*W[p+1].y + o[2]*W[p+2].y
                              + o[3]*W[p+3].y + o[4]*W[p+4].y + o[5]*W[p+5].y;
                    float vex = e[0]*W[p].x + e[1]*W[p+1].x + e[2]*W[p+2].x + e[3]*W[p+3].x
                              + e[4]*W[p+4].x + e[5]*W[p+5].x + e[6]*W[p+6].x;
                    float vey = e[0]*W[p].y + e[1]*W[p+1].y + e[2]*W[p+2].y + e[3]*W[p+3].y
                              + e[4]*W[p+4].y + e[5]*W[p+5].y + e[6]*W[p+6].y;
                    if (!y_int) {
                        int gr = 2 * Y0 - 5 + 2 * i;
                        bool ok0 = (unsigned)gr       < 256u;
                        bool ok1 = (unsigned)(gr + 1) < 256u;
                        vox = ok0 ? vox : 0.f;  voy = ok0 ? voy : 0.f;
                        vex = ok1 ? vex : 0.f;  vey = ok1 ? vey : 0.f;
                    }
                    float2 ro, re;
                    ro.x = (vox >= 0.f) ? vox : 0.2f * vox;
                    ro.y = (voy >= 0.f) ? voy : 0.2f * voy;
                    re.x = (vex >= 0.f) ? vex : 0.2f * vex;
                    re.y = (vey >= 0.f) ? vey : 0.2f * vey;
                    *reinterpret_cast<float2*>(adst + (2 * p)     * PT) = ro;
                    *reinterpret_cast<float2*>(adst + (2 * p + 1) * PT) = re;
                }
            }
        }
    }
    __syncthreads();

    // dn taps as packed pairs: pdn[m] = (dn[2m], dn[2m+1])
    u64 pdn[6];
    #pragma unroll
    for (int m = 0; m < 6; m++) pdn[m] = pk2(fdn[2*m], fdn[2*m + 1]);

    // ---- S3: horizontal dn-conv, stride-2 -> t2[74][32]; packed f32x2 ----
    // unit (t, ar): outputs X = 8t..8t+7; reads a[ar][16t..16t+27] as 7 float4
    // (= 14 pairs pel[n]); facc[q] = sum_n pdn[n-q]*pel[n], acc = hadd(facc).
    #pragma unroll
    for (int it = 0; it < 2; it++) {
        int u = tid + 256 * it;
        if (u < 4 * 74) {
            int t  = u / 74;
            int ar = u - t * 74;
            const float4* row = reinterpret_cast<const float4*>(s_a + ar * PT + 16 * t);
            u64 facc[8] = {0,0,0,0,0,0,0,0};
            #pragma unroll
            for (int j = 0; j < 7; j++) {
                float4 qv = row[j];
                u64 pelA = pk2(qv.x, qv.y);
                u64 pelB = pk2(qv.z, qv.w);
                const int nA = 2 * j, nB = 2 * j + 1;
                #pragma unroll
                for (int q = 0; q < 8; q++) {
                    int mA = nA - q;
                    if (mA >= 0 && mA < 6) facc[q] = ffma2(pdn[mA], pelA, facc[q]);
                    int mB = nB - q;
                    if (mB >= 0 && mB < 6) facc[q] = ffma2(pdn[mB], pelB, facc[q]);
                }
            }
            float acc[8];
            #pragma unroll
            for (int q = 0; q < 8; q++) {
                float lo, hi; upk2(facc[q], lo, hi);
                acc[q] = lo + hi;
            }
            float* dst = s_t2 + ar * P2 + 8 * t;
            *reinterpret_cast<float4*>(dst)     = make_float4(acc[0],acc[1],acc[2],acc[3]);
            *reinterpret_cast<float4*>(dst + 4) = make_float4(acc[4],acc[5],acc[6],acc[7]);
        }
    }
    __syncthreads();

    // ---- S4: vertical dn-conv, stride-2 -> out; packed f32x2 over col pairs ----
    // thread: 4 rows x 2 cols; R2[k] = (t2[2y0+k][2cp], t2[..][2cp+1]) (LDS.64);
    // (sx,sy)_q = sum_k bcast(dn[k]) * R2[k+2q].
    if (tid < 128) {
        int cp = tid & 15;
        int yg = tid >> 4;
        // unpack dn scalars from pdn
        float dns[12];
        #pragma unroll
        for (int m = 0; m < 6; m++) upk2(pdn[m], dns[2*m], dns[2*m + 1]);
        const float* base = s_t2 + (8 * yg) * P2 + 2 * cp;
        u64 R2[18];
        #pragma unroll
        for (int k = 0; k < 18; k++)
            R2[k] = *reinterpret_cast<const u64*>(base + k * P2);
        u64 facc[4] = {0,0,0,0};
        #pragma unroll
        for (int k = 0; k < 12; k++) {
            u64 d2 = pk2(dns[k], dns[k]);
            #pragma unroll
            for (int q = 0; q < 4; q++)
                facc[q] = ffma2(d2, R2[k + 2*q], facc[q]);
        }
        float* op = out + ((size_t)bc * 128 + (Y0 + 4 * yg)) * 128 + X0 + 2 * cp;
        #pragma unroll
        for (int q = 0; q < 4; q++)
            *reinterpret_cast<u64*>(op + q * 128) = facc[q];
    }
}

extern "C" void kernel_launch(void* const* d_in, const int* in_sizes, int n_in,
                              void* d_out, int out_size)
{
    const float* x    = (const float*)d_in[0];   // (8,64,130,130) fp32
    const float* bias = (const float*)d_in[1];   // (64,) fp32
    const float* fup  = (const float*)d_in[2];   // (12,) fp32
    const float* fdn  = (const float*)d_in[3];   // (12,) fp32
    float* out = (float*)d_out;                  // (8,64,128,128) fp32

    dim3 grid(16, 512);
    upfirdn2d_fused_kernel<<<grid, NTHR>>>(x, bias, fup, fdn, out);
}